// round 16
// baseline (speedup 1.0000x reference)
#include <cuda_runtime.h>
#include <cuda_bf16.h>
#include <math.h>

#define NATOMS 20000
#define NEDGES 400000
#define NB 32
#define MDIM 9          // (LMAX+1)^2
#define FEAT (MDIM*NB)  // 288
#define NRBF 20
#define TSTEPS 2

// ---------------- static device scratch (no runtime allocation) ----------------
__device__ float g_CG[729];                       // real-basis CG, [a*81+b*9+c]
__device__ int   g_cstart[10];                    // nnz list grouped by c
__device__ int   g_ab[729];
__device__ float g_v[729];
__device__ int   g_rowptr[NATOMS + 1];
__device__ float g_dx[(size_t)NATOMS * FEAT];               // 23 MB
__device__ float g_tbc[(size_t)NEDGES * 81];                // 129.6 MB
__device__ float g_Wl[(size_t)TSTEPS * NEDGES * 96];        // 307 MB

// ---------------- CG construction (mirrors reference exactly, fp64) ----------------
__device__ double dfact(int n) { double r = 1.0; for (int i = 2; i <= n; ++i) r *= (double)i; return r; }

__device__ double cg_complex_d(int j1, int m1, int j2, int m2, int j3, int m3) {
    if (m3 != m1 + m2) return 0.0;
    if (j3 < abs(j1 - j2) || j3 > j1 + j2) return 0.0;
    double pref = sqrt((2.0 * j3 + 1.0) * dfact(j1 + j2 - j3) * dfact(j1 - j2 + j3) *
                       dfact(-j1 + j2 + j3) / dfact(j1 + j2 + j3 + 1));
    pref *= sqrt(dfact(j1 + m1) * dfact(j1 - m1) * dfact(j2 + m2) * dfact(j2 - m2) *
                 dfact(j3 + m3) * dfact(j3 - m3));
    int kmin = max(0, max(j2 - j3 - m1, j1 + m2 - j3));
    int kmax = min(j1 + j2 - j3, min(j1 - m1, j2 + m2));
    double s = 0.0;
    for (int k = kmin; k <= kmax; ++k) {
        s += ((k & 1) ? -1.0 : 1.0) /
             (dfact(k) * dfact(j1 + j2 - j3 - k) * dfact(j1 - m1 - k) * dfact(j2 + m2 - k) *
              dfact(j3 - j2 + m1 + k) * dfact(j3 - j1 - m2 + k));
    }
    return pref * s;
}

// U matrix entry: row = l+m convention of the reference
__device__ void u_ent(int l, int row, int col, double& re, double& im) {
    re = 0.0; im = 0.0;
    const double s = 0.70710678118654752440;
    int m = row - l;
    if (m == 0) {
        if (col == l) re = 1.0;
    } else if (m > 0) {
        if (col == l + m)      re = ((m & 1) ? -s : s);
        else if (col == l - m) re = s;
    } else {
        int mu = -m;
        if (col == l + m)      im = s;               //  i/sqrt2
        else if (col == l - m) im = ((mu & 1) ? s : -s); // -i*(-1)^mu/sqrt2
    }
}

__device__ __forceinline__ int l_of(int a) { return (a == 0) ? 0 : ((a < 4) ? 1 : 2); }

// one thread per (a,b,c) entry; 128-thread blocks to respect the register file
__global__ void __launch_bounds__(128) init_cg_kernel() {
    int tid = blockIdx.x * blockDim.x + threadIdx.x;
    if (tid >= 729) return;
    int a = tid / 81, b = (tid / 9) % 9, cc = tid % 9;
    int l1 = l_of(a), l2 = l_of(b), l3 = l_of(cc);
    float out = 0.0f;
    if ((((l1 + l2 + l3) & 1) == 0) && l3 >= abs(l1 - l2) && l3 <= l1 + l2) {
        int ar = a - l1 * l1, br = b - l2 * l2, cr = cc - l3 * l3;
        double re = 0.0;
        for (int i = 0; i < 2 * l1 + 1; ++i)
            for (int j = 0; j < 2 * l2 + 1; ++j)
                for (int k = 0; k < 2 * l3 + 1; ++k) {
                    double cg = cg_complex_d(l1, i - l1, l2, j - l2, l3, k - l3);
                    if (cg == 0.0) continue;
                    double u1r, u1i, u2r, u2i, u3r, u3i;
                    u_ent(l1, ar, i, u1r, u1i);
                    u_ent(l2, br, j, u2r, u2i);
                    u_ent(l3, cr, k, u3r, u3i);
                    u3i = -u3i;  // conjugate
                    double pr = u1r * u2r - u1i * u2i;
                    double pi = u1r * u2i + u1i * u2r;
                    double qr = pr * u3r - pi * u3i;
                    re += qr * cg;
                }
        out = (float)re;
    }
    g_CG[tid] = out;
}

// compact nonzero (a,b) pairs grouped by c — separate launch orders it after init_cg
__global__ void __launch_bounds__(32) build_cg_list_kernel() {
    if (threadIdx.x != 0 || blockIdx.x != 0) return;
    int cnt = 0;
    for (int cc = 0; cc < 9; ++cc) {
        g_cstart[cc] = cnt;
        for (int a = 0; a < 9; ++a)
            for (int b = 0; b < 9; ++b) {
                float v = g_CG[a * 81 + b * 9 + cc];
                if (fabsf(v) > 1e-6f) { g_ab[cnt] = (a << 4) | b; g_v[cnt] = v; ++cnt; }
            }
    }
    g_cstart[9] = cnt;
}

// ---------------- CSR rowptr from sorted idx_i ----------------
__global__ void __launch_bounds__(256) build_rowptr_kernel(const int* __restrict__ idx_i) {
    int e = blockIdx.x * blockDim.x + threadIdx.x;
    if (e < NEDGES) {
        int cur = idx_i[e];
        int prev = (e == 0) ? -1 : idx_i[e - 1];
        for (int a = prev + 1; a <= cur; ++a) g_rowptr[a] = e;
    } else if (e == NEDGES) {
        int last = idx_i[NEDGES - 1];
        for (int a = last + 1; a <= NATOMS; ++a) g_rowptr[a] = NEDGES;
    }
}

// ---------------- x init: emb gather into m=0, zeros elsewhere ----------------
__global__ void __launch_bounds__(256) init_x_kernel(const int* __restrict__ Z,
                                                     const float* __restrict__ emb,
                                                     float* __restrict__ x) {
    int g = blockIdx.x * blockDim.x + threadIdx.x;
    if (g >= NATOMS * FEAT) return;
    int atom = g / FEAT, p = g % FEAT;
    x[g] = (p < NB) ? emb[Z[atom] * NB + p] : 0.0f;
}

// ---------------- per-edge geometry precompute: tbc (t-invariant) + Wl (per t) ----------------
__global__ void __launch_bounds__(128) precompute_edges_kernel(const float* __restrict__ r_ij,
                                                               const float* __restrict__ Wf,
                                                               const float* __restrict__ bf) {
    int lane = threadIdx.x & 31;
    int warp = (blockIdx.x * blockDim.x + threadIdx.x) >> 5;
    int nwarps = (gridDim.x * blockDim.x) >> 5;
    const float c1 = 0.4886025119029199f;
    const float c2 = 1.0925484305920792f;
    for (int e = warp; e < NEDGES; e += nwarps) {
        float rx = r_ij[3 * e + 0], ry = r_ij[3 * e + 1], rz = r_ij[3 * e + 2];
        float d = sqrtf(rx * rx + ry * ry + rz * rz);
        float inv = 1.0f / d;
        float x = rx * inv, y = ry * inv, z = rz * inv;
        float Y[9];
        Y[0] = 0.28209479177387814f;
        Y[1] = c1 * y; Y[2] = c1 * z; Y[3] = c1 * x;
        Y[4] = c2 * x * y; Y[5] = c2 * y * z;
        Y[6] = 0.31539156525252005f * (3.0f * z * z - 1.0f);
        Y[7] = c2 * x * z;
        Y[8] = 0.5462742152960396f * (x * x - y * y);

        // tbc[b*9+c] = sum_a Y[a] * CG[a][b][c]
        for (int bc = lane; bc < 81; bc += 32) {
            float s = 0.0f;
            #pragma unroll
            for (int a = 0; a < 9; ++a) s += Y[a] * g_CG[a * 81 + bc];
            g_tbc[(size_t)e * 81 + bc] = s;
        }

        // radial basis + cutoff
        float fcut = (d < 5.0f) ? 0.5f * (cosf(d * (float)M_PI / 5.0f) + 1.0f) : 0.0f;
        float rad[NRBF];
        #pragma unroll
        for (int k = 0; k < NRBF; ++k) {
            float dd = d - (5.0f / 19.0f) * (float)k;
            rad[k] = expf(-7.22f * dd * dd);
        }
        // Wl[t][r] = (rad . Wf[t][r] + bf[t][r]) * fcut,  r in [0,96)
        #pragma unroll
        for (int tt = 0; tt < TSTEPS; ++tt) {
            for (int r = lane; r < 96; r += 32) {
                const float* wrow = Wf + (size_t)tt * 96 * NRBF + (size_t)r * NRBF;
                float s = bf[tt * 96 + r];
                #pragma unroll
                for (int k = 0; k < NRBF; ++k) s += rad[k] * wrow[k];
                g_Wl[(size_t)tt * NEDGES * 96 + (size_t)e * 96 + r] = s * fcut;
            }
        }
    }
}

// ---------------- edge phase: gather + contract + segment-sum (one block per atom) ----------------
__global__ void __launch_bounds__(FEAT) edge_kernel(const int* __restrict__ idx_j,
                                                    const float* __restrict__ x, int t) {
    __shared__ float xj_sh[FEAT];
    __shared__ float wl_sh[96];
    __shared__ float tbc_sh[81];
    int atom = blockIdx.x;
    int tid = threadIdx.x;
    int c = tid >> 5, n = tid & 31;
    int lc = (c == 0) ? 0 : ((c < 4) ? 1 : 2);
    int wlo = lc * 32 + n;
    int rs = g_rowptr[atom], re = g_rowptr[atom + 1];
    const float* Wl_t = g_Wl + (size_t)t * NEDGES * 96;
    float acc = 0.0f;
    for (int e = rs; e < re; ++e) {
        int j = __ldg(&idx_j[e]);
        xj_sh[tid] = x[(size_t)j * FEAT + tid];
        if (tid < 96) wl_sh[tid] = Wl_t[(size_t)e * 96 + tid];
        else if (tid < 96 + 81) tbc_sh[tid - 96] = g_tbc[(size_t)e * 81 + (tid - 96)];
        __syncthreads();
        float s = 0.0f;
        #pragma unroll
        for (int b = 0; b < 9; ++b) s += tbc_sh[b * 9 + c] * xj_sh[b * 32 + n];
        acc += s * wl_sh[wlo];
        __syncthreads();
    }
    g_dx[(size_t)atom * FEAT + tid] = acc;
}

// ---------------- node phase: one warp per atom, lane = channel ----------------
__global__ void __launch_bounds__(256) node_kernel(const float* __restrict__ Wm1,
                                                   const float* __restrict__ Wm2,
                                                   const float* __restrict__ Wm3,
                                                   const float* __restrict__ Wg,
                                                   const float* __restrict__ bg,
                                                   float* __restrict__ x) {
    __shared__ float w1[1024], w2[1024], w3[1024];  // transposed: w[n*32+k] = Wm[k*32+n]
    __shared__ float wg[3072];                      // wg[n*96+r] = Wg[r*32+n]
    __shared__ float bgs[96];
    __shared__ float shA[8][FEAT];
    __shared__ float shB[8][FEAT];

    int tid = threadIdx.x;
    for (int i = tid; i < 1024; i += 256) {
        int n = i >> 5, k = i & 31;
        w1[i] = Wm1[k * 32 + n];
        w2[i] = Wm2[k * 32 + n];
        w3[i] = Wm3[k * 32 + n];
    }
    for (int i = tid; i < 3072; i += 256) {
        int n = i / 96, r = i % 96;
        wg[i] = Wg[r * 32 + n];
    }
    if (tid < 96) bgs[tid] = bg[tid];
    __syncthreads();

    int w = tid >> 5, lane = tid & 31;
    int atom = blockIdx.x * 8 + w;
    if (atom >= NATOMS) return;
    float* A = shA[w];
    float* B = shB[w];

    // load dx (lane = n axis)
    float d0[9];
    #pragma unroll
    for (int c = 0; c < 9; ++c) {
        d0[c] = g_dx[(size_t)atom * FEAT + c * 32 + lane];
        A[c * 32 + lane] = d0[c];
    }
    __syncwarp();

    // ddx[c][k=lane] = sum_n dx[c][n] * Wm1[k][n]
    float dd[9];
    #pragma unroll
    for (int c = 0; c < 9; ++c) {
        float s = 0.0f;
        #pragma unroll
        for (int n = 0; n < 32; ++n) s += A[c * 32 + n] * w1[n * 32 + lane];
        dd[c] = s;
    }
    #pragma unroll
    for (int c = 0; c < 9; ++c) B[c * 32 + lane] = dd[c];
    __syncwarp();

    // dx2[c][n=lane] = dx[c] + sum_{a,b} CG[a,b,c] * dx[a][lane] * ddx[b][lane]
    float d2[9];
    #pragma unroll
    for (int c = 0; c < 9; ++c) {
        float s = d0[c];
        int s0 = g_cstart[c], s1 = g_cstart[c + 1];
        for (int idx = s0; idx < s1; ++idx) {
            int ab = g_ab[idx];
            s += g_v[idx] * A[(ab >> 4) * 32 + lane] * B[(ab & 15) * 32 + lane];
        }
        d2[c] = s;
    }
    __syncwarp();
    #pragma unroll
    for (int c = 0; c < 9; ++c) A[c * 32 + lane] = d2[c];
    __syncwarp();

    // dx3[c][k=lane] = sum_n dx2[c][n] * Wm2[k][n]
    float d3[9];
    #pragma unroll
    for (int c = 0; c < 9; ++c) {
        float s = 0.0f;
        #pragma unroll
        for (int n = 0; n < 32; ++n) s += A[c * 32 + n] * w2[n * 32 + lane];
        d3[c] = s;
    }
    B[lane] = d3[0];
    __syncwarp();

    // gate h[l][k=lane] = sigmoid( sum_n dx3[0][n] * Wg[l*32+k][n] + bg[l*32+k] )
    float h[3];
    #pragma unroll
    for (int l = 0; l < 3; ++l) {
        float s = bgs[l * 32 + lane];
        #pragma unroll
        for (int n = 0; n < 32; ++n) s += B[n] * wg[n * 96 + l * 32 + lane];
        h[l] = 1.0f / (1.0f + expf(-s));
    }
    __syncwarp();

    // dx4 = dx3 * h[lidx(c)],  then dx5[c][k=lane] = sum_n dx4[c][n] * Wm3[k][n]
    #pragma unroll
    for (int c = 0; c < 9; ++c) {
        int lc = (c == 0) ? 0 : ((c < 4) ? 1 : 2);
        A[c * 32 + lane] = d3[c] * h[lc];
    }
    __syncwarp();
    #pragma unroll
    for (int c = 0; c < 9; ++c) {
        float s = 0.0f;
        #pragma unroll
        for (int n = 0; n < 32; ++n) s += A[c * 32 + n] * w3[n * 32 + lane];
        x[(size_t)atom * FEAT + c * 32 + lane] += s;
    }
}

// ---------------- launch ----------------
extern "C" void kernel_launch(void* const* d_in, const int* in_sizes, int n_in,
                              void* d_out, int out_size) {
    const int*   Z     = (const int*)d_in[0];
    const float* r_ij  = (const float*)d_in[1];
    const int*   idx_i = (const int*)d_in[2];
    const int*   idx_j = (const int*)d_in[3];
    const float* emb   = (const float*)d_in[4];
    const float* Wf    = (const float*)d_in[5];
    const float* bf    = (const float*)d_in[6];
    const float* Wm1   = (const float*)d_in[7];
    const float* Wm2   = (const float*)d_in[8];
    const float* Wm3   = (const float*)d_in[9];
    const float* Wg    = (const float*)d_in[10];
    const float* bg    = (const float*)d_in[11];
    float* x = (float*)d_out;

    init_cg_kernel<<<(729 + 127) / 128, 128>>>();
    build_cg_list_kernel<<<1, 32>>>();
    build_rowptr_kernel<<<(NEDGES + 1 + 255) / 256, 256>>>(idx_i);
    init_x_kernel<<<(NATOMS * FEAT + 255) / 256, 256>>>(Z, emb, x);
    precompute_edges_kernel<<<1480, 128>>>(r_ij, Wf, bf);

    for (int t = 0; t < TSTEPS; ++t) {
        edge_kernel<<<NATOMS, FEAT>>>(idx_j, x, t);
        node_kernel<<<(NATOMS + 7) / 8, 256>>>(Wm1 + t * 1024, Wm2 + t * 1024, Wm3 + t * 1024,
                                               Wg + t * 3072, bg + t * 96, x);
    }
}

// round 17
// speedup vs baseline: 1.4599x; 1.4599x over previous
#include <cuda_runtime.h>
#include <cuda_bf16.h>
#include <math.h>

#define NATOMS 20000
#define NEDGES 400000
#define NB 32
#define MDIM 9          // (LMAX+1)^2
#define FEAT (MDIM*NB)  // 288
#define NRBF 20
#define TSTEPS 2

// ---------------- static device scratch (no runtime allocation) ----------------
__device__ float g_CG[729];                       // real-basis CG, [a*81+b*9+c]
__device__ int   g_cstart[10];                    // nnz list grouped by c
__device__ int   g_ab[729];
__device__ float g_v[729];
__device__ int   g_rowptr[NATOMS + 1];
__device__ float g_dx[(size_t)NATOMS * FEAT];               // 23 MB
__device__ float g_tbc[(size_t)NEDGES * 81];                // 129.6 MB
__device__ float g_Wl[(size_t)TSTEPS * NEDGES * 96];        // 307 MB

__device__ __constant__ double c_fact[16] = {
    1.0, 1.0, 2.0, 6.0, 24.0, 120.0, 720.0, 5040.0, 40320.0, 362880.0,
    3628800.0, 39916800.0, 479001600.0, 6227020800.0, 87178291200.0, 1307674368000.0};

// ---------------- CG construction (mirrors reference, fp64, factorial table) ----------------
__device__ __forceinline__ double cg_complex_d(int j1, int m1, int j2, int m2, int j3, int m3) {
    if (m3 != m1 + m2) return 0.0;
    if (j3 < abs(j1 - j2) || j3 > j1 + j2) return 0.0;
    double pref = sqrt((2.0 * j3 + 1.0) * c_fact[j1 + j2 - j3] * c_fact[j1 - j2 + j3] *
                       c_fact[-j1 + j2 + j3] / c_fact[j1 + j2 + j3 + 1]);
    pref *= sqrt(c_fact[j1 + m1] * c_fact[j1 - m1] * c_fact[j2 + m2] * c_fact[j2 - m2] *
                 c_fact[j3 + m3] * c_fact[j3 - m3]);
    int kmin = max(0, max(j2 - j3 - m1, j1 + m2 - j3));
    int kmax = min(j1 + j2 - j3, min(j1 - m1, j2 + m2));
    double s = 0.0;
    for (int k = kmin; k <= kmax; ++k) {
        s += ((k & 1) ? -1.0 : 1.0) /
             (c_fact[k] * c_fact[j1 + j2 - j3 - k] * c_fact[j1 - m1 - k] * c_fact[j2 + m2 - k] *
              c_fact[j3 - j2 + m1 + k] * c_fact[j3 - j1 - m2 + k]);
    }
    return pref * s;
}

__device__ __forceinline__ void u_ent(int l, int row, int col, double& re, double& im) {
    re = 0.0; im = 0.0;
    const double s = 0.70710678118654752440;
    int m = row - l;
    if (m == 0) {
        if (col == l) re = 1.0;
    } else if (m > 0) {
        if (col == l + m)      re = ((m & 1) ? -s : s);
        else if (col == l - m) re = s;
    } else {
        int mu = -m;
        if (col == l + m)      im = s;               //  i/sqrt2
        else if (col == l - m) im = ((mu & 1) ? s : -s); // -i*(-1)^mu/sqrt2
    }
}

__device__ __forceinline__ int l_of(int a) { return (a == 0) ? 0 : ((a < 4) ? 1 : 2); }

// one WARP per (a,b,c) entry; lanes split the (i,j,k) triples, warp-reduce
__global__ void __launch_bounds__(256) init_cg_kernel() {
    int gw = (blockIdx.x * blockDim.x + threadIdx.x) >> 5;
    int lane = threadIdx.x & 31;
    if (gw >= 729) return;
    int a = gw / 81, b = (gw / 9) % 9, cc = gw % 9;
    int l1 = l_of(a), l2 = l_of(b), l3 = l_of(cc);
    bool ok = ((((l1 + l2 + l3) & 1) == 0) && l3 >= abs(l1 - l2) && l3 <= l1 + l2);
    double re = 0.0;
    if (ok) {
        int n2 = 2 * l2 + 1, n3 = 2 * l3 + 1;
        int nt = (2 * l1 + 1) * n2 * n3;
        int ar = a - l1 * l1, br = b - l2 * l2, cr = cc - l3 * l3;
        for (int idx = lane; idx < nt; idx += 32) {
            int i = idx / (n2 * n3), j = (idx / n3) % n2, k = idx % n3;
            double cg = cg_complex_d(l1, i - l1, l2, j - l2, l3, k - l3);
            if (cg == 0.0) continue;
            double u1r, u1i, u2r, u2i, u3r, u3i;
            u_ent(l1, ar, i, u1r, u1i);
            u_ent(l2, br, j, u2r, u2i);
            u_ent(l3, cr, k, u3r, u3i);
            u3i = -u3i;  // conjugate
            double pr = u1r * u2r - u1i * u2i;
            double pi = u1r * u2i + u1i * u2r;
            re += (pr * u3r - pi * u3i) * cg;
        }
    }
    #pragma unroll
    for (int off = 16; off; off >>= 1) re += __shfl_xor_sync(0xffffffff, re, off);
    if (lane == 0) g_CG[gw] = ok ? (float)re : 0.0f;
}

// compact nonzero (a,b) pairs grouped by c — separate launch orders it after init_cg
__global__ void __launch_bounds__(32) build_cg_list_kernel() {
    if (threadIdx.x != 0 || blockIdx.x != 0) return;
    int cnt = 0;
    for (int cc = 0; cc < 9; ++cc) {
        g_cstart[cc] = cnt;
        for (int a = 0; a < 9; ++a)
            for (int b = 0; b < 9; ++b) {
                float v = g_CG[a * 81 + b * 9 + cc];
                if (fabsf(v) > 1e-6f) { g_ab[cnt] = (a << 4) | b; g_v[cnt] = v; ++cnt; }
            }
    }
    g_cstart[9] = cnt;
}

// ---------------- CSR rowptr from sorted idx_i ----------------
__global__ void __launch_bounds__(256) build_rowptr_kernel(const int* __restrict__ idx_i) {
    int e = blockIdx.x * blockDim.x + threadIdx.x;
    if (e < NEDGES) {
        int cur = idx_i[e];
        int prev = (e == 0) ? -1 : idx_i[e - 1];
        for (int a = prev + 1; a <= cur; ++a) g_rowptr[a] = e;
    } else if (e == NEDGES) {
        int last = idx_i[NEDGES - 1];
        for (int a = last + 1; a <= NATOMS; ++a) g_rowptr[a] = NEDGES;
    }
}

// ---------------- x init ----------------
__global__ void __launch_bounds__(256) init_x_kernel(const int* __restrict__ Z,
                                                     const float* __restrict__ emb,
                                                     float* __restrict__ x) {
    int g = blockIdx.x * blockDim.x + threadIdx.x;
    if (g >= NATOMS * FEAT) return;
    int atom = g / FEAT, p = g % FEAT;
    x[g] = (p < NB) ? emb[Z[atom] * NB + p] : 0.0f;
}

// ---------------- per-edge geometry precompute: tbc (t-invariant) + Wl (per t) ----------------
__global__ void __launch_bounds__(128) precompute_edges_kernel(const float* __restrict__ r_ij,
                                                               const float* __restrict__ Wf,
                                                               const float* __restrict__ bf) {
    int lane = threadIdx.x & 31;
    int warp = (blockIdx.x * blockDim.x + threadIdx.x) >> 5;
    int nwarps = (gridDim.x * blockDim.x) >> 5;
    const float c1 = 0.4886025119029199f;
    const float c2 = 1.0925484305920792f;
    for (int e = warp; e < NEDGES; e += nwarps) {
        float rx = r_ij[3 * e + 0], ry = r_ij[3 * e + 1], rz = r_ij[3 * e + 2];
        float d = sqrtf(rx * rx + ry * ry + rz * rz);
        float inv = 1.0f / d;
        float x = rx * inv, y = ry * inv, z = rz * inv;
        float Y[9];
        Y[0] = 0.28209479177387814f;
        Y[1] = c1 * y; Y[2] = c1 * z; Y[3] = c1 * x;
        Y[4] = c2 * x * y; Y[5] = c2 * y * z;
        Y[6] = 0.31539156525252005f * (3.0f * z * z - 1.0f);
        Y[7] = c2 * x * z;
        Y[8] = 0.5462742152960396f * (x * x - y * y);

        // tbc[b*9+c] = sum_a Y[a] * CG[a][b][c]
        for (int bc = lane; bc < 81; bc += 32) {
            float s = 0.0f;
            #pragma unroll
            for (int a = 0; a < 9; ++a) s += Y[a] * g_CG[a * 81 + bc];
            g_tbc[(size_t)e * 81 + bc] = s;
        }

        // radial basis + cutoff
        float fcut = (d < 5.0f) ? 0.5f * (cosf(d * (float)M_PI / 5.0f) + 1.0f) : 0.0f;
        float rad[NRBF];
        #pragma unroll
        for (int k = 0; k < NRBF; ++k) {
            float dd = d - (5.0f / 19.0f) * (float)k;
            rad[k] = expf(-7.22f * dd * dd);
        }
        #pragma unroll
        for (int tt = 0; tt < TSTEPS; ++tt) {
            for (int r = lane; r < 96; r += 32) {
                const float* wrow = Wf + (size_t)tt * 96 * NRBF + (size_t)r * NRBF;
                float s = bf[tt * 96 + r];
                #pragma unroll
                for (int k = 0; k < NRBF; ++k) s += rad[k] * wrow[k];
                g_Wl[(size_t)tt * NEDGES * 96 + (size_t)e * 96 + r] = s * fcut;
            }
        }
    }
}

// ---------------- edge phase: block per atom, warp per edge, register xj ----------------
__global__ void __launch_bounds__(FEAT) edge_kernel(const int* __restrict__ idx_j,
                                                    const float* __restrict__ x, int t) {
    __shared__ float red[9][FEAT];     // cross-warp reduction
    __shared__ float tbc_sh[9][96];    // warp-private tbc staging (81 used)
    int atom = blockIdx.x;
    int tid = threadIdx.x;
    int w = tid >> 5, lane = tid & 31;
    int rs = g_rowptr[atom], re = g_rowptr[atom + 1];
    const float* Wl_t = g_Wl + (size_t)t * NEDGES * 96;
    float acc[9];
    #pragma unroll
    for (int c = 0; c < 9; ++c) acc[c] = 0.0f;
    float* tb = tbc_sh[w];

    for (int e = rs + w; e < re; e += 9) {
        int j = __ldg(&idx_j[e]);
        // stage tbc (coalesced within warp)
        const float* tsrc = g_tbc + (size_t)e * 81;
        if (lane < 27) {
            tb[lane]      = tsrc[lane];
            tb[lane + 27] = tsrc[lane + 27];
            tb[lane + 54] = tsrc[lane + 54];
        }
        // wl direct to registers (coalesced)
        const float* wsrc = Wl_t + (size_t)e * 96;
        float wl0 = __ldg(&wsrc[lane]);
        float wl1 = __ldg(&wsrc[32 + lane]);
        float wl2 = __ldg(&wsrc[64 + lane]);
        // xj direct to registers (9 coalesced 128B loads)
        const float* xj = x + (size_t)j * FEAT;
        float xr[9];
        #pragma unroll
        for (int b = 0; b < 9; ++b) xr[b] = __ldg(&xj[b * 32 + lane]);
        __syncwarp();
        float s[9];
        #pragma unroll
        for (int c = 0; c < 9; ++c) s[c] = 0.0f;
        #pragma unroll
        for (int b = 0; b < 9; ++b) {
            #pragma unroll
            for (int c = 0; c < 9; ++c) s[c] += tb[b * 9 + c] * xr[b];
        }
        acc[0] += s[0] * wl0;
        #pragma unroll
        for (int c = 1; c < 4; ++c) acc[c] += s[c] * wl1;
        #pragma unroll
        for (int c = 4; c < 9; ++c) acc[c] += s[c] * wl2;
        __syncwarp();
    }
    #pragma unroll
    for (int c = 0; c < 9; ++c) red[w][c * 32 + lane] = acc[c];
    __syncthreads();
    float s = 0.0f;
    #pragma unroll
    for (int w2 = 0; w2 < 9; ++w2) s += red[w2][tid];
    g_dx[(size_t)atom * FEAT + tid] = s;
}

// ---------------- node phase: one warp per atom, lane = channel ----------------
__global__ void __launch_bounds__(256) node_kernel(const float* __restrict__ Wm1,
                                                   const float* __restrict__ Wm2,
                                                   const float* __restrict__ Wm3,
                                                   const float* __restrict__ Wg,
                                                   const float* __restrict__ bg,
                                                   float* __restrict__ x) {
    __shared__ float w1[1024], w2[1024], w3[1024];  // transposed: w[n*32+k] = Wm[k*32+n]
    __shared__ float wg[3072];                      // wg[n*96+r] = Wg[r*32+n]
    __shared__ float bgs[96];
    __shared__ float shA[8][FEAT];
    __shared__ float shB[8][FEAT];

    int tid = threadIdx.x;
    for (int i = tid; i < 1024; i += 256) {
        int n = i >> 5, k = i & 31;
        w1[i] = Wm1[k * 32 + n];
        w2[i] = Wm2[k * 32 + n];
        w3[i] = Wm3[k * 32 + n];
    }
    for (int i = tid; i < 3072; i += 256) {
        int n = i / 96, r = i % 96;
        wg[i] = Wg[r * 32 + n];
    }
    if (tid < 96) bgs[tid] = bg[tid];
    __syncthreads();

    int w = tid >> 5, lane = tid & 31;
    int atom = blockIdx.x * 8 + w;
    if (atom >= NATOMS) return;
    float* A = shA[w];
    float* B = shB[w];

    float d0[9];
    #pragma unroll
    for (int c = 0; c < 9; ++c) {
        d0[c] = g_dx[(size_t)atom * FEAT + c * 32 + lane];
        A[c * 32 + lane] = d0[c];
    }
    __syncwarp();

    float dd[9];
    #pragma unroll
    for (int c = 0; c < 9; ++c) {
        float s = 0.0f;
        #pragma unroll
        for (int n = 0; n < 32; ++n) s += A[c * 32 + n] * w1[n * 32 + lane];
        dd[c] = s;
    }
    #pragma unroll
    for (int c = 0; c < 9; ++c) B[c * 32 + lane] = dd[c];
    __syncwarp();

    float d2[9];
    #pragma unroll
    for (int c = 0; c < 9; ++c) {
        float s = d0[c];
        int s0 = g_cstart[c], s1 = g_cstart[c + 1];
        for (int idx = s0; idx < s1; ++idx) {
            int ab = g_ab[idx];
            s += g_v[idx] * A[(ab >> 4) * 32 + lane] * B[(ab & 15) * 32 + lane];
        }
        d2[c] = s;
    }
    __syncwarp();
    #pragma unroll
    for (int c = 0; c < 9; ++c) A[c * 32 + lane] = d2[c];
    __syncwarp();

    float d3[9];
    #pragma unroll
    for (int c = 0; c < 9; ++c) {
        float s = 0.0f;
        #pragma unroll
        for (int n = 0; n < 32; ++n) s += A[c * 32 + n] * w2[n * 32 + lane];
        d3[c] = s;
    }
    B[lane] = d3[0];
    __syncwarp();

    float h[3];
    #pragma unroll
    for (int l = 0; l < 3; ++l) {
        float s = bgs[l * 32 + lane];
        #pragma unroll
        for (int n = 0; n < 32; ++n) s += B[n] * wg[n * 96 + l * 32 + lane];
        h[l] = 1.0f / (1.0f + expf(-s));
    }
    __syncwarp();

    #pragma unroll
    for (int c = 0; c < 9; ++c) {
        int lc = (c == 0) ? 0 : ((c < 4) ? 1 : 2);
        A[c * 32 + lane] = d3[c] * h[lc];
    }
    __syncwarp();
    #pragma unroll
    for (int c = 0; c < 9; ++c) {
        float s = 0.0f;
        #pragma unroll
        for (int n = 0; n < 32; ++n) s += A[c * 32 + n] * w3[n * 32 + lane];
        x[(size_t)atom * FEAT + c * 32 + lane] += s;
    }
}

// ---------------- launch ----------------
extern "C" void kernel_launch(void* const* d_in, const int* in_sizes, int n_in,
                              void* d_out, int out_size) {
    const int*   Z     = (const int*)d_in[0];
    const float* r_ij  = (const float*)d_in[1];
    const int*   idx_i = (const int*)d_in[2];
    const int*   idx_j = (const int*)d_in[3];
    const float* emb   = (const float*)d_in[4];
    const float* Wf    = (const float*)d_in[5];
    const float* bf    = (const float*)d_in[6];
    const float* Wm1   = (const float*)d_in[7];
    const float* Wm2   = (const float*)d_in[8];
    const float* Wm3   = (const float*)d_in[9];
    const float* Wg    = (const float*)d_in[10];
    const float* bg    = (const float*)d_in[11];
    float* x = (float*)d_out;

    init_cg_kernel<<<(729 * 32 + 255) / 256, 256>>>();
    build_cg_list_kernel<<<1, 32>>>();
    build_rowptr_kernel<<<(NEDGES + 1 + 255) / 256, 256>>>(idx_i);
    init_x_kernel<<<(NATOMS * FEAT + 255) / 256, 256>>>(Z, emb, x);
    precompute_edges_kernel<<<1480, 128>>>(r_ij, Wf, bf);

    for (int t = 0; t < TSTEPS; ++t) {
        edge_kernel<<<NATOMS, FEAT>>>(idx_j, x, t);
        node_kernel<<<(NATOMS + 7) / 8, 256>>>(Wm1 + t * 1024, Wm2 + t * 1024, Wm3 + t * 1024,
                                               Wg + t * 3072, bg + t * 96, x);
    }
}